// round 2
// baseline (speedup 1.0000x reference)
#include <cuda_runtime.h>

// Model_21569325760600: structure-module forward.
//   inputs (metadata order):
//     0 output_0          float32 [N,17,1]
//     1 output_1          float32 [N,3,3]
//     2 pos               float32 [N,3]
//     3 ss                int32   [N]
//     4 residue_type      int32   [N]
//     5 rigid_transforms  float32 [3,22,8,4,3]
//     6 rigid_groups      float32 [3,22,24,3]
//     7 transforms_dep    int32   [22,8]
//     8 rigids_dep        int32   [22,24]
//   output: concat( R [N,24,3], opr0 [N,4,3] )  float32, N*84 elements
//
// Layout: 8 lanes per residue (one lane per rigid transform slot), 4 residues
// per warp. Dependency-chain and atom gathers done with __shfl_sync.
// Lookup tables staged once per (persistent) block into padded shared memory.

#define NRES    22
#define MAX_SS  3
#define NE      (NRES * MAX_SS)   // 66 table entries
#define TSTRIDE 100               // padded stride for 96-float transform entries
#define RSTRIDE 73                // padded stride for 72-float rigid entries

__device__ __forceinline__ void combine_tf(const float* __restrict__ X,
                                           const float* __restrict__ Y,
                                           float* __restrict__ C) {
    // X, Y, C: 12 floats. rows 0-2 = rotation (row-major), 9..11 = translation.
    // C_rot = X_rot @ Y_rot ; C_t = X_rot @ Y_t + X_t
#pragma unroll
    for (int i = 0; i < 3; i++) {
#pragma unroll
        for (int j = 0; j < 3; j++) {
            C[3*i+j] = X[3*i+0]*Y[0+j] + X[3*i+1]*Y[3+j] + X[3*i+2]*Y[6+j];
        }
        C[9+i] = X[3*i+0]*Y[9] + X[3*i+1]*Y[10] + X[3*i+2]*Y[11] + X[9+i];
    }
}

__global__ __launch_bounds__(256) void struct_module_kernel(
    const float* __restrict__ out0,      // [N,17]
    const float* __restrict__ out1,      // [N,9]
    const float* __restrict__ pos,       // [N,3]
    const int*   __restrict__ ss,        // [N]
    const int*   __restrict__ rtype,     // [N]
    const float* __restrict__ g_trans,   // [66,8,12]
    const float* __restrict__ g_rigid,   // [66,24,3]
    const int*   __restrict__ g_tdep,    // [22,8]
    const int*   __restrict__ g_rdep,    // [22,24]
    float* __restrict__ outR,            // [N,24,3]
    float* __restrict__ outO,            // [N,12]
    int N)
{
    __shared__ float s_t[NE * TSTRIDE];   // 6600 f = 26400 B
    __shared__ float s_r[NE * RSTRIDE];   // 4818 f = 19272 B
    __shared__ int   s_tdep[NRES * 8];    // 704 B
    __shared__ int   s_rdep[NRES * 24];   // 2112 B

    // ---- stage tables (coalesced reads, padded smem writes) ----
    for (int idx = threadIdx.x; idx < NE * 96; idx += blockDim.x)
        s_t[(idx / 96) * TSTRIDE + (idx % 96)] = g_trans[idx];
    for (int idx = threadIdx.x; idx < NE * 72; idx += blockDim.x)
        s_r[(idx / 72) * RSTRIDE + (idx % 72)] = g_rigid[idx];
    for (int idx = threadIdx.x; idx < NRES * 8; idx += blockDim.x)
        s_tdep[idx] = g_tdep[idx];
    for (int idx = threadIdx.x; idx < NRES * 24; idx += blockDim.x)
        s_rdep[idx] = g_rdep[idx];
    __syncthreads();

    const int lane = threadIdx.x & 31;
    const int li   = lane & 7;        // transform slot owned by this lane
    const int base = lane & ~7;       // first lane of this residue-group
    const int warpGlobal = (blockIdx.x * blockDim.x + threadIdx.x) >> 5;
    const int totalWarps = (gridDim.x * blockDim.x) >> 5;

    for (int r0 = warpGlobal * 4; r0 < N; r0 += totalWarps * 4) {
        int r = r0 + (lane >> 3);
        bool valid = (r < N);
        int rc = valid ? r : 0;

        int my_ss = ss[rc];
        int my_rt = rtype[rc];
        int e = my_ss * NRES + my_rt;

        // ---- load this lane's rigid transform T from smem (16B aligned) ----
        float T[12];
        {
            const float4* tp = reinterpret_cast<const float4*>(&s_t[e * TSTRIDE + li * 12]);
            float4 a = tp[0], b = tp[1], c = tp[2];
            T[0]=a.x; T[1]=a.y; T[2]=a.z;  T[3]=a.w;
            T[4]=b.x; T[5]=b.y; T[6]=b.z;  T[7]=b.w;
            T[8]=c.x; T[9]=c.y; T[10]=c.z; T[11]=c.w;
        }

        // ---- build local transform and combine with T -> o ----
        float o[12];
        if (li == 0) {
            // backbone frame from output_1 + pos
            const float* p1 = out1 + (size_t)rc * 9;
            float v0x = p1[0], v0y = p1[1], v0z = p1[2];
            float v1x = p1[3], v1y = p1[4], v1z = p1[5];
            float n0 = sqrtf(v0x*v0x + v0y*v0y + v0z*v0z);
            float i0 = 1.0f / fmaxf(n0, 1e-6f);
            float e0x = v0x*i0, e0y = v0y*i0, e0z = v0z*i0;
            float d = e0x*v1x + e0y*v1y + e0z*v1z;
            float u1x = v1x - e0x*d, u1y = v1y - e0y*d, u1z = v1z - e0z*d;
            float n1 = sqrtf(u1x*u1x + u1y*u1y + u1z*u1z);
            float i1 = 1.0f / fmaxf(n1, 1e-6f);
            float e1x = u1x*i1, e1y = u1y*i1, e1z = u1z*i1;
            float e2x = e0y*e1z - e0z*e1y;
            float e2y = e0z*e1x - e0x*e1z;
            float e2z = e0x*e1y - e0y*e1x;
            float B[12];
            // rot columns are (e0, e1, e2): B[3i+j] = e_j[i]
            B[0]=e0x; B[1]=e1x; B[2]=e2x;
            B[3]=e0y; B[4]=e1y; B[5]=e2y;
            B[6]=e0z; B[7]=e1z; B[8]=e2z;
            const float* pp = pos + (size_t)rc * 3;
            B[9]  = 0.1f * p1[6] + pp[0];
            B[10] = 0.1f * p1[7] + pp[1];
            B[11] = 0.1f * p1[8] + pp[2];
            combine_tf(T, B, o);
        } else {
            // torsion frame: rot = [[1,0,0],[0,c,-s],[0,s,c]], t = 0
            float c0 = out0[(size_t)rc * 17 + 2*(li-1)];
            float s0 = out0[(size_t)rc * 17 + 2*(li-1) + 1];
            float inv = 1.0f / fmaxf(sqrtf(c0*c0 + s0*s0), 1e-6f);
            float c = c0 * inv, s = s0 * inv;
            // C[i][0] = T[i][0]; C[i][1] = T[i][1]*c + T[i][2]*s;
            // C[i][2] = -T[i][1]*s + T[i][2]*c; t = T.t
#pragma unroll
            for (int i = 0; i < 3; i++) {
                o[3*i+0] = T[3*i+0];
                o[3*i+1] = T[3*i+1]*c + T[3*i+2]*s;
                o[3*i+2] = T[3*i+2]*c - T[3*i+1]*s;
                o[9+i]   = T[9+i];
            }
        }

        // ---- dependency chain: 7 sequential steps, shuffle prev from owner ----
        int my_tdep = s_tdep[my_rt * 8 + li];
        int src = base + my_tdep;
#pragma unroll
        for (int stp = 1; stp < 8; stp++) {
            float p[12];
#pragma unroll
            for (int k = 0; k < 12; k++)
                p[k] = __shfl_sync(0xffffffffu, o[k], src, 32);
            float nw[12];
            combine_tf(p, o, nw);
            bool upd = (li == stp);
#pragma unroll
            for (int k = 0; k < 12; k++)
                o[k] = upd ? nw[k] : o[k];
        }

        // ---- atom gather: 24 atoms, 3 per lane ----
#pragma unroll
        for (int asub = 0; asub < 3; asub++) {
            int a = li * 3 + asub;
            int rd = s_rdep[my_rt * 24 + a];
            int gsrc = base + rd;
            float g[12];
#pragma unroll
            for (int k = 0; k < 12; k++)
                g[k] = __shfl_sync(0xffffffffu, o[k], gsrc, 32);
            const float* rg = &s_r[e * RSTRIDE + a * 3];
            float vx = rg[0], vy = rg[1], vz = rg[2];
            float R0 = g[0]*vx + g[1]*vy + g[2]*vz + g[9];
            float R1 = g[3]*vx + g[4]*vy + g[5]*vz + g[10];
            float R2 = g[6]*vx + g[7]*vy + g[8]*vz + g[11];
            if (valid) {
                float* op = outR + (size_t)r * 72 + a * 3;
                op[0] = R0; op[1] = R1; op[2] = R2;
            }
        }

        // ---- opr[:,0] output (lane 0 of each group) ----
        if (li == 0 && valid) {
            float* op = outO + (size_t)r * 12;
#pragma unroll
            for (int k = 0; k < 12; k++)
                op[k] = o[k];
        }
    }
}

extern "C" void kernel_launch(void* const* d_in, const int* in_sizes, int n_in,
                              void* d_out, int out_size) {
    const float* out0 = (const float*)d_in[0];
    const float* out1 = (const float*)d_in[1];
    const float* posp = (const float*)d_in[2];
    const int*   ssp  = (const int*)d_in[3];
    const int*   rtp  = (const int*)d_in[4];
    const float* gt   = (const float*)d_in[5];
    const float* gr   = (const float*)d_in[6];
    const int*   td   = (const int*)d_in[7];
    const int*   rd   = (const int*)d_in[8];
    int N = in_sizes[3];                  // ss element count
    float* R = (float*)d_out;
    float* O = R + (size_t)N * 72;

    // persistent grid: ~4 blocks/SM on 148 SMs
    struct_module_kernel<<<592, 256>>>(out0, out1, posp, ssp, rtp,
                                       gt, gr, td, rd, R, O, N);
}

// round 3
// speedup vs baseline: 1.1054x; 1.1054x over previous
#include <cuda_runtime.h>

// Model_21569325760600: structure-module forward.
// 8 lanes per residue, 4 residues per warp. Chain + atom gather via shfl.
// Tables read through L1 (LDG). Outputs staged in smem -> coalesced STG.128.

#define NRES    22
#define MAX_SS  3

__device__ __forceinline__ void combine_tf(const float* __restrict__ X,
                                           const float* __restrict__ Y,
                                           float* __restrict__ C) {
#pragma unroll
    for (int i = 0; i < 3; i++) {
#pragma unroll
        for (int j = 0; j < 3; j++) {
            C[3*i+j] = X[3*i+0]*Y[0+j] + X[3*i+1]*Y[3+j] + X[3*i+2]*Y[6+j];
        }
        C[9+i] = X[3*i+0]*Y[9] + X[3*i+1]*Y[10] + X[3*i+2]*Y[11] + X[9+i];
    }
}

__global__ __launch_bounds__(256) void struct_module_kernel(
    const float* __restrict__ out0,      // [N,17]
    const float* __restrict__ out1,      // [N,9]
    const float* __restrict__ pos,       // [N,3]
    const int*   __restrict__ ss,        // [N]
    const int*   __restrict__ rtype,     // [N]
    const float* __restrict__ g_trans,   // [66,8,12]
    const float* __restrict__ g_rigid,   // [66,24,3]
    const int*   __restrict__ g_tdep,    // [22,8]
    const int*   __restrict__ g_rdep,    // [22,24]
    float* __restrict__ outR,            // [N,72]
    float* __restrict__ outO,            // [N,12]
    int N)
{
    __shared__ int   s_tdep[NRES * 8];
    __shared__ int   s_rdep[NRES * 24];
    // per-warp output staging: 4 residues * (72 R + 12 O) floats
    __shared__ float s_out[8][336];

    for (int idx = threadIdx.x; idx < NRES * 8; idx += blockDim.x)
        s_tdep[idx] = g_tdep[idx];
    for (int idx = threadIdx.x; idx < NRES * 24; idx += blockDim.x)
        s_rdep[idx] = g_rdep[idx];
    __syncthreads();

    const int lane = threadIdx.x & 31;
    const int w    = threadIdx.x >> 5;    // warp in block
    const int li   = lane & 7;            // transform slot owned by this lane
    const int grp  = lane >> 3;           // residue sub-group 0..3
    const int base = lane & ~7;
    const int warpGlobal = (blockIdx.x * blockDim.x + threadIdx.x) >> 5;
    const int totalWarps = (gridDim.x * blockDim.x) >> 5;

    for (int r0 = warpGlobal * 4; r0 < N; r0 += totalWarps * 4) {
        int r = r0 + grp;
        bool valid = (r < N);
        int rc = valid ? r : 0;

        int my_ss = __ldg(&ss[rc]);
        int my_rt = __ldg(&rtype[rc]);
        int e = my_ss * NRES + my_rt;

        // ---- lane's rigid transform T: 3 x LDG.128 (48B-aligned rows) ----
        float T[12];
        {
            const float4* tp = reinterpret_cast<const float4*>(g_trans + e * 96 + li * 12);
            float4 a = __ldg(tp + 0), b = __ldg(tp + 1), c = __ldg(tp + 2);
            T[0]=a.x; T[1]=a.y; T[2]=a.z;  T[3]=a.w;
            T[4]=b.x; T[5]=b.y; T[6]=b.z;  T[7]=b.w;
            T[8]=c.x; T[9]=c.y; T[10]=c.z; T[11]=c.w;
        }

        // ---- local transform combined with T -> o ----
        float o[12];
        if (li == 0) {
            const float* p1 = out1 + (size_t)rc * 9;
            float v0x = p1[0], v0y = p1[1], v0z = p1[2];
            float v1x = p1[3], v1y = p1[4], v1z = p1[5];
            float n0 = sqrtf(v0x*v0x + v0y*v0y + v0z*v0z);
            float i0 = 1.0f / fmaxf(n0, 1e-6f);
            float e0x = v0x*i0, e0y = v0y*i0, e0z = v0z*i0;
            float d = e0x*v1x + e0y*v1y + e0z*v1z;
            float u1x = v1x - e0x*d, u1y = v1y - e0y*d, u1z = v1z - e0z*d;
            float n1 = sqrtf(u1x*u1x + u1y*u1y + u1z*u1z);
            float i1 = 1.0f / fmaxf(n1, 1e-6f);
            float e1x = u1x*i1, e1y = u1y*i1, e1z = u1z*i1;
            float e2x = e0y*e1z - e0z*e1y;
            float e2y = e0z*e1x - e0x*e1z;
            float e2z = e0x*e1y - e0y*e1x;
            float B[12];
            B[0]=e0x; B[1]=e1x; B[2]=e2x;
            B[3]=e0y; B[4]=e1y; B[5]=e2y;
            B[6]=e0z; B[7]=e1z; B[8]=e2z;
            const float* pp = pos + (size_t)rc * 3;
            B[9]  = 0.1f * p1[6] + pp[0];
            B[10] = 0.1f * p1[7] + pp[1];
            B[11] = 0.1f * p1[8] + pp[2];
            combine_tf(T, B, o);
        } else {
            float c0 = out0[(size_t)rc * 17 + 2*(li-1)];
            float s0 = out0[(size_t)rc * 17 + 2*(li-1) + 1];
            float inv = 1.0f / fmaxf(sqrtf(c0*c0 + s0*s0), 1e-6f);
            float c = c0 * inv, s = s0 * inv;
#pragma unroll
            for (int i = 0; i < 3; i++) {
                o[3*i+0] = T[3*i+0];
                o[3*i+1] = T[3*i+1]*c + T[3*i+2]*s;
                o[3*i+2] = T[3*i+2]*c - T[3*i+1]*s;
                o[9+i]   = T[9+i];
            }
        }

        // ---- dependency chain: 7 sequential steps via shfl ----
        int my_tdep = s_tdep[my_rt * 8 + li];
        int src = base + my_tdep;
#pragma unroll
        for (int stp = 1; stp < 8; stp++) {
            float p[12];
#pragma unroll
            for (int k = 0; k < 12; k++)
                p[k] = __shfl_sync(0xffffffffu, o[k], src, 32);
            float nw[12];
            combine_tf(p, o, nw);
            bool upd = (li == stp);
#pragma unroll
            for (int k = 0; k < 12; k++)
                o[k] = upd ? nw[k] : o[k];
        }

        // ---- atom gather: 24 atoms, 3 per lane; results -> smem staging ----
#pragma unroll
        for (int asub = 0; asub < 3; asub++) {
            int a = li * 3 + asub;
            int rd = s_rdep[my_rt * 24 + a];
            int gsrc = base + rd;
            float g[12];
#pragma unroll
            for (int k = 0; k < 12; k++)
                g[k] = __shfl_sync(0xffffffffu, o[k], gsrc, 32);
            const float* rg = g_rigid + e * 72 + a * 3;
            float vx = __ldg(rg + 0), vy = __ldg(rg + 1), vz = __ldg(rg + 2);
            // bank-conflict-free: addr = grp*72 + 9*li + 3*asub + k -> 32 distinct banks
            float* sp = &s_out[w][grp * 72 + a * 3];
            sp[0] = g[0]*vx + g[1]*vy + g[2]*vz + g[9];
            sp[1] = g[3]*vx + g[4]*vy + g[5]*vz + g[10];
            sp[2] = g[6]*vx + g[7]*vy + g[8]*vz + g[11];
        }

        // ---- opr[:,0] -> smem staging ----
        if (li == 0) {
            float* sp = &s_out[w][288 + grp * 12];
#pragma unroll
            for (int k = 0; k < 12; k++)
                sp[k] = o[k];
        }
        __syncwarp();

        // ---- coalesced flush: R = 72 float4, O = 12 float4 ----
        int rem = N - r0;
        int nR4 = (rem >= 4) ? 72 : rem * 18;   // rem*72 floats / 4
        int nO4 = (rem >= 4) ? 12 : rem * 3;
        const float4* s4 = reinterpret_cast<const float4*>(&s_out[w][0]);
        float4* dR = reinterpret_cast<float4*>(outR + (size_t)r0 * 72);
        for (int i = lane; i < nR4; i += 32)
            dR[i] = s4[i];
        const float4* s4o = reinterpret_cast<const float4*>(&s_out[w][288]);
        float4* dO = reinterpret_cast<float4*>(outO + (size_t)r0 * 12);
        if (lane < nO4)
            dO[lane] = s4o[lane];
        __syncwarp();
    }
}

extern "C" void kernel_launch(void* const* d_in, const int* in_sizes, int n_in,
                              void* d_out, int out_size) {
    const float* out0 = (const float*)d_in[0];
    const float* out1 = (const float*)d_in[1];
    const float* posp = (const float*)d_in[2];
    const int*   ssp  = (const int*)d_in[3];
    const int*   rtp  = (const int*)d_in[4];
    const float* gt   = (const float*)d_in[5];
    const float* gr   = (const float*)d_in[6];
    const int*   td   = (const int*)d_in[7];
    const int*   rd   = (const int*)d_in[8];
    int N = in_sizes[3];
    float* R = (float*)d_out;
    float* O = R + (size_t)N * 72;

    struct_module_kernel<<<592, 256>>>(out0, out1, posp, ssp, rtp,
                                       gt, gr, td, rd, R, O, N);
}

// round 4
// speedup vs baseline: 1.2799x; 1.1578x over previous
#include <cuda_runtime.h>

// Model_21569325760600: structure-module forward, L1-wavefront-optimized.
// 8 lanes/residue, 4 residues/warp. Chain via pointer-jumping shuffles.
// Tables reformatted by a prolog kernel into line-coalesced layouts.

#define NRES  22
#define NE    66
#define FULLM 0xffffffffu

// reformatted tables: [e][chunk(3)][li(8)][4] floats = 96 floats per entry
__device__ __align__(16) float d_t2[NE * 96];
__device__ __align__(16) float d_r2[NE * 96];

__global__ void reformat_kernel(const float* __restrict__ g_trans,   // [66,8,12]
                                const float* __restrict__ g_rigid) { // [66,24,3]
    int e = blockIdx.x;          // 0..65
    int t = threadIdx.x;         // 0..95
    int j4 = t >> 5;             // chunk 0..2
    int li = (t >> 2) & 7;
    int k  = t & 3;
    d_t2[e * 96 + t] = g_trans[e * 96 + li * 12 + j4 * 4 + k];
    // rigid: chunk == asub, atom a = li*3+asub, pad k==3 with 0
    d_r2[e * 96 + t] = (k < 3) ? g_rigid[e * 72 + (li * 3 + j4) * 3 + k] : 0.0f;
}

__device__ __forceinline__ void combine_tf(const float* __restrict__ X,
                                           const float* __restrict__ Y,
                                           float* __restrict__ C) {
#pragma unroll
    for (int i = 0; i < 3; i++) {
#pragma unroll
        for (int j = 0; j < 3; j++)
            C[3*i+j] = X[3*i+0]*Y[0+j] + X[3*i+1]*Y[3+j] + X[3*i+2]*Y[6+j];
        C[9+i] = X[3*i+0]*Y[9] + X[3*i+1]*Y[10] + X[3*i+2]*Y[11] + X[9+i];
    }
}

__global__ __launch_bounds__(256) void struct_module_kernel(
    const float* __restrict__ out0,      // [N,17]
    const float* __restrict__ out1,      // [N,9]
    const float* __restrict__ pos,       // [N,3]
    const int*   __restrict__ ss,        // [N]
    const int*   __restrict__ rtype,     // [N]
    const int*   __restrict__ g_tdep,    // [22,8]
    const int*   __restrict__ g_rdep,    // [22,24]
    float* __restrict__ outR,            // [N,72]
    float* __restrict__ outO,            // [N,12]
    int N)
{
    __shared__ int   s_tdep[NRES * 8];
    __shared__ int   s_rdep[NRES * 24];
    __shared__ float s_out[8][336];

    for (int idx = threadIdx.x; idx < NRES * 8; idx += blockDim.x)
        s_tdep[idx] = g_tdep[idx];
    for (int idx = threadIdx.x; idx < NRES * 24; idx += blockDim.x)
        s_rdep[idx] = g_rdep[idx];
    __syncthreads();

    const int lane = threadIdx.x & 31;
    const int w    = threadIdx.x >> 5;
    const int li   = lane & 7;
    const int grp  = lane >> 3;
    const int base = lane & ~7;
    const int warpGlobal = (blockIdx.x * blockDim.x + threadIdx.x) >> 5;
    const int totalWarps = (gridDim.x * blockDim.x) >> 5;

    for (int r0 = warpGlobal * 4; r0 < N; r0 += totalWarps * 4) {
        int rem = N - r0;                       // >= 1
        int nres = (rem >= 4) ? 4 : rem;
        int r = r0 + grp;
        bool valid = (r < N);
        int rc = valid ? r : (N - 1);

        int my_ss = __ldg(&ss[rc]);
        int my_rt = __ldg(&rtype[rc]);
        int e = my_ss * NRES + my_rt;

        // ---- T from reformatted table: 3 LDG.128, 1 line per group each ----
        float T[12];
        {
            const float4* tp = reinterpret_cast<const float4*>(d_t2) + e * 24;
            float4 a = tp[li], b = tp[8 + li], c = tp[16 + li];
            T[0]=a.x; T[1]=a.y; T[2]=a.z;  T[3]=a.w;
            T[4]=b.x; T[5]=b.y; T[6]=b.z;  T[7]=b.w;
            T[8]=c.x; T[9]=c.y; T[10]=c.z; T[11]=c.w;
        }

        // ---- coalesced bb inputs: out1 (36 floats) + pos (12 floats) ----
        int nf1 = nres * 9;
        int nfp = nres * 3;
        float a0 = (lane < nf1)      ? out1[(size_t)r0 * 9 + lane]      : 0.0f;
        float a1 = (lane + 32 < nf1) ? out1[(size_t)r0 * 9 + 32 + lane] : 0.0f;
        float p0 = (lane < nfp)      ? pos[(size_t)r0 * 3 + lane]       : 0.0f;

        float v[9];
#pragma unroll
        for (int j = 0; j < 9; j++)
            v[j] = __shfl_sync(FULLM, a0, (9 * grp + j) & 31, 32);
#pragma unroll
        for (int j = 5; j < 9; j++) {
            int hs = 9 * grp + j - 32;
            float hi = __shfl_sync(FULLM, a1, hs < 0 ? 0 : hs, 32);
            if (9 * grp + j >= 32) v[j] = hi;
        }
        float pv[3];
#pragma unroll
        for (int k = 0; k < 3; k++)
            pv[k] = __shfl_sync(FULLM, p0, 3 * grp + k, 32);

        // ---- local transform combined with T -> o ----
        float o[12];
        if (li == 0) {
            float v0x = v[0], v0y = v[1], v0z = v[2];
            float v1x = v[3], v1y = v[4], v1z = v[5];
            float n0 = sqrtf(v0x*v0x + v0y*v0y + v0z*v0z);
            float i0 = 1.0f / fmaxf(n0, 1e-6f);
            float e0x = v0x*i0, e0y = v0y*i0, e0z = v0z*i0;
            float d = e0x*v1x + e0y*v1y + e0z*v1z;
            float u1x = v1x - e0x*d, u1y = v1y - e0y*d, u1z = v1z - e0z*d;
            float n1 = sqrtf(u1x*u1x + u1y*u1y + u1z*u1z);
            float i1 = 1.0f / fmaxf(n1, 1e-6f);
            float e1x = u1x*i1, e1y = u1y*i1, e1z = u1z*i1;
            float e2x = e0y*e1z - e0z*e1y;
            float e2y = e0z*e1x - e0x*e1z;
            float e2z = e0x*e1y - e0y*e1x;
            float B[12];
            B[0]=e0x; B[1]=e1x; B[2]=e2x;
            B[3]=e0y; B[4]=e1y; B[5]=e2y;
            B[6]=e0z; B[7]=e1z; B[8]=e2z;
            B[9]  = 0.1f * v[6] + pv[0];
            B[10] = 0.1f * v[7] + pv[1];
            B[11] = 0.1f * v[8] + pv[2];
            combine_tf(T, B, o);
        } else {
            float c0 = out0[(size_t)rc * 17 + 2*(li-1)];
            float s0 = out0[(size_t)rc * 17 + 2*(li-1) + 1];
            float inv = 1.0f / fmaxf(sqrtf(c0*c0 + s0*s0), 1e-6f);
            float c = c0 * inv, s = s0 * inv;
#pragma unroll
            for (int i = 0; i < 3; i++) {
                o[3*i+0] = T[3*i+0];
                o[3*i+1] = T[3*i+1]*c + T[3*i+2]*s;
                o[3*i+2] = T[3*i+2]*c - T[3*i+1]*s;
                o[9+i]   = T[9+i];
            }
        }

        // ---- dependency chain via pointer jumping ----
        // Reference semantics: step i (i=1..7) uses slot tdep[i]'s value:
        // final if tdep[i] < i (slot already updated), base otherwise.
        int dd = s_tdep[my_rt * 8 + li];
        int ptr;
        float val[12];
        {
            int s0l = base + dd;
            float pb[12];
#pragma unroll
            for (int k = 0; k < 12; k++)
                pb[k] = __shfl_sync(FULLM, o[k], s0l, 32);   // everyone still holds base
            float nv[12];
            combine_tf(pb, o, nv);
            bool imm = (li != 0) && (dd >= li);   // parent contribution is base -> compose now
            bool done = (li == 0) || imm;
            ptr = done ? -1 : (base + dd);
#pragma unroll
            for (int k = 0; k < 12; k++)
                val[k] = imm ? nv[k] : o[k];
        }
        // live parent chain is strictly decreasing (<= 7 edges): 3 jump rounds
#pragma unroll
        for (int rnd = 0; rnd < 3; rnd++) {
            int ps = (ptr >= 0) ? ptr : lane;
            float pvv[12];
#pragma unroll
            for (int k = 0; k < 12; k++)
                pvv[k] = __shfl_sync(FULLM, val[k], ps, 32);
            int pp = __shfl_sync(FULLM, ptr, ps, 32);
            float nv[12];
            combine_tf(pvv, val, nv);
            bool live = (ptr >= 0);
#pragma unroll
            for (int k = 0; k < 12; k++)
                val[k] = live ? nv[k] : val[k];
            ptr = live ? pp : ptr;
        }

        // ---- atom gather: 3 atoms per lane, rigid vecs from reformatted table ----
        const float4* rp = reinterpret_cast<const float4*>(d_r2) + e * 24;
#pragma unroll
        for (int asub = 0; asub < 3; asub++) {
            int a = li * 3 + asub;
            int rd = s_rdep[my_rt * 24 + a];
            int gsrc = base + rd;
            float g[12];
#pragma unroll
            for (int k = 0; k < 12; k++)
                g[k] = __shfl_sync(FULLM, val[k], gsrc, 32);
            float4 rv = rp[asub * 8 + li];            // 1 line per group
            float* sp = &s_out[w][grp * 72 + a * 3];  // bank-conflict-free
            sp[0] = g[0]*rv.x + g[1]*rv.y + g[2]*rv.z + g[9];
            sp[1] = g[3]*rv.x + g[4]*rv.y + g[5]*rv.z + g[10];
            sp[2] = g[6]*rv.x + g[7]*rv.y + g[8]*rv.z + g[11];
        }

        // ---- opr[:,0] staging (lane li==0 holds final slot-0 = its val) ----
        if (li == 0) {
            float* sp = &s_out[w][288 + grp * 12];
#pragma unroll
            for (int k = 0; k < 12; k++)
                sp[k] = val[k];
        }
        __syncwarp();

        // ---- coalesced flush ----
        int nR4 = nres * 18;
        int nO4 = nres * 3;
        const float4* s4 = reinterpret_cast<const float4*>(&s_out[w][0]);
        float4* dR = reinterpret_cast<float4*>(outR + (size_t)r0 * 72);
        for (int i = lane; i < nR4; i += 32)
            dR[i] = s4[i];
        const float4* s4o = reinterpret_cast<const float4*>(&s_out[w][288]);
        float4* dO = reinterpret_cast<float4*>(outO + (size_t)r0 * 12);
        if (lane < nO4)
            dO[lane] = s4o[lane];
        __syncwarp();
    }
}

extern "C" void kernel_launch(void* const* d_in, const int* in_sizes, int n_in,
                              void* d_out, int out_size) {
    const float* out0 = (const float*)d_in[0];
    const float* out1 = (const float*)d_in[1];
    const float* posp = (const float*)d_in[2];
    const int*   ssp  = (const int*)d_in[3];
    const int*   rtp  = (const int*)d_in[4];
    const float* gt   = (const float*)d_in[5];
    const float* gr   = (const float*)d_in[6];
    const int*   td   = (const int*)d_in[7];
    const int*   rd   = (const int*)d_in[8];
    int N = in_sizes[3];
    float* R = (float*)d_out;
    float* O = R + (size_t)N * 72;

    reformat_kernel<<<NE, 96>>>(gt, gr);
    struct_module_kernel<<<592, 256>>>(out0, out1, posp, ssp, rtp,
                                       td, rd, R, O, N);
}

// round 5
// speedup vs baseline: 1.3773x; 1.0761x over previous
#include <cuda_runtime.h>

// Model_21569325760600: structure-module forward.
// 8 lanes/residue, 4 residues/warp. Chain via pointer-jumping shuffles with
// warp-uniform early exit. Tables reformatted into line-coalesced layouts.
// R staged in smem -> STG.128 flush; opr0 stored directly from leader lanes.

#define NRES  22
#define NE    66
#define FULLM 0xffffffffu

// reformatted tables: [e][chunk(3)][li(8)][4] floats = 96 floats per entry
__device__ __align__(16) float d_t2[NE * 96];
__device__ __align__(16) float d_r2[NE * 96];

__global__ void reformat_kernel(const float* __restrict__ g_trans,   // [66,8,12]
                                const float* __restrict__ g_rigid) { // [66,24,3]
    int e = blockIdx.x;          // 0..65
    int t = threadIdx.x;         // 0..95
    int j4 = t >> 5;             // chunk 0..2
    int li = (t >> 2) & 7;
    int k  = t & 3;
    d_t2[e * 96 + t] = g_trans[e * 96 + li * 12 + j4 * 4 + k];
    d_r2[e * 96 + t] = (k < 3) ? g_rigid[e * 72 + (li * 3 + j4) * 3 + k] : 0.0f;
}

__device__ __forceinline__ void combine_tf(const float* __restrict__ X,
                                           const float* __restrict__ Y,
                                           float* __restrict__ C) {
#pragma unroll
    for (int i = 0; i < 3; i++) {
#pragma unroll
        for (int j = 0; j < 3; j++)
            C[3*i+j] = X[3*i+0]*Y[0+j] + X[3*i+1]*Y[3+j] + X[3*i+2]*Y[6+j];
        C[9+i] = X[3*i+0]*Y[9] + X[3*i+1]*Y[10] + X[3*i+2]*Y[11] + X[9+i];
    }
}

__global__ __launch_bounds__(256) void struct_module_kernel(
    const float* __restrict__ out0,      // [N,17]
    const float* __restrict__ out1,      // [N,9]
    const float* __restrict__ pos,       // [N,3]
    const int*   __restrict__ ss,        // [N]
    const int*   __restrict__ rtype,     // [N]
    const int*   __restrict__ g_tdep,    // [22,8]
    const int*   __restrict__ g_rdep,    // [22,24]
    float* __restrict__ outR,            // [N,72]
    float* __restrict__ outO,            // [N,12]
    int N)
{
    __shared__ int   s_tdep[NRES * 8];
    __shared__ int   s_rdep[NRES * 24];
    __shared__ float s_out[8][288];      // R staging only

    for (int idx = threadIdx.x; idx < NRES * 8; idx += blockDim.x)
        s_tdep[idx] = g_tdep[idx];
    for (int idx = threadIdx.x; idx < NRES * 24; idx += blockDim.x)
        s_rdep[idx] = g_rdep[idx];
    __syncthreads();

    const int lane = threadIdx.x & 31;
    const int w    = threadIdx.x >> 5;
    const int li   = lane & 7;
    const int grp  = lane >> 3;
    const int base = lane & ~7;
    const int warpGlobal = (blockIdx.x * blockDim.x + threadIdx.x) >> 5;
    const int totalWarps = (gridDim.x * blockDim.x) >> 5;

    for (int r0 = warpGlobal * 4; r0 < N; r0 += totalWarps * 4) {
        int rem = N - r0;
        int nres = (rem >= 4) ? 4 : rem;
        int r = r0 + grp;
        bool valid = (r < N);
        int rc = valid ? r : (N - 1);

        int my_ss = __ldg(&ss[rc]);
        int my_rt = __ldg(&rtype[rc]);
        int e = my_ss * NRES + my_rt;

        // ---- T from reformatted table: 3 LDG.128, 1 line per group each ----
        float T[12];
        {
            const float4* tp = reinterpret_cast<const float4*>(d_t2) + e * 24;
            float4 a = tp[li], b = tp[8 + li], c = tp[16 + li];
            T[0]=a.x; T[1]=a.y; T[2]=a.z;  T[3]=a.w;
            T[4]=b.x; T[5]=b.y; T[6]=b.z;  T[7]=b.w;
            T[8]=c.x; T[9]=c.y; T[10]=c.z; T[11]=c.w;
        }

        // ---- coalesced bb inputs: out1 (36 floats) + pos (12 floats) ----
        int nf1 = nres * 9;
        int nfp = nres * 3;
        float a0 = (lane < nf1)      ? out1[(size_t)r0 * 9 + lane]      : 0.0f;
        float a1 = (lane + 32 < nf1) ? out1[(size_t)r0 * 9 + 32 + lane] : 0.0f;
        float p0 = (lane < nfp)      ? pos[(size_t)r0 * 3 + lane]       : 0.0f;

        float v[9];
#pragma unroll
        for (int j = 0; j < 9; j++)
            v[j] = __shfl_sync(FULLM, a0, (9 * grp + j) & 31, 32);
#pragma unroll
        for (int j = 5; j < 9; j++) {
            int hs = 9 * grp + j - 32;
            float hi = __shfl_sync(FULLM, a1, hs < 0 ? 0 : hs, 32);
            if (9 * grp + j >= 32) v[j] = hi;
        }
        float pv[3];
#pragma unroll
        for (int k = 0; k < 3; k++)
            pv[k] = __shfl_sync(FULLM, p0, 3 * grp + k, 32);

        // ---- local transform combined with T -> o ----
        float o[12];
        if (li == 0) {
            float v0x = v[0], v0y = v[1], v0z = v[2];
            float v1x = v[3], v1y = v[4], v1z = v[5];
            float n2a = v0x*v0x + v0y*v0y + v0z*v0z;
            float i0 = rsqrtf(fmaxf(n2a, 1e-12f));   // == 1/max(sqrt,1e-6)
            float e0x = v0x*i0, e0y = v0y*i0, e0z = v0z*i0;
            float d = e0x*v1x + e0y*v1y + e0z*v1z;
            float u1x = v1x - e0x*d, u1y = v1y - e0y*d, u1z = v1z - e0z*d;
            float n2b = u1x*u1x + u1y*u1y + u1z*u1z;
            float i1 = rsqrtf(fmaxf(n2b, 1e-12f));
            float e1x = u1x*i1, e1y = u1y*i1, e1z = u1z*i1;
            float e2x = e0y*e1z - e0z*e1y;
            float e2y = e0z*e1x - e0x*e1z;
            float e2z = e0x*e1y - e0y*e1x;
            float B[12];
            B[0]=e0x; B[1]=e1x; B[2]=e2x;
            B[3]=e0y; B[4]=e1y; B[5]=e2y;
            B[6]=e0z; B[7]=e1z; B[8]=e2z;
            B[9]  = 0.1f * v[6] + pv[0];
            B[10] = 0.1f * v[7] + pv[1];
            B[11] = 0.1f * v[8] + pv[2];
            combine_tf(T, B, o);
        } else {
            float c0 = out0[(size_t)rc * 17 + 2*(li-1)];
            float s0 = out0[(size_t)rc * 17 + 2*(li-1) + 1];
            float inv = rsqrtf(fmaxf(c0*c0 + s0*s0, 1e-12f));
            float c = c0 * inv, s = s0 * inv;
#pragma unroll
            for (int i = 0; i < 3; i++) {
                o[3*i+0] = T[3*i+0];
                o[3*i+1] = T[3*i+1]*c + T[3*i+2]*s;
                o[3*i+2] = T[3*i+2]*c - T[3*i+1]*s;
                o[9+i]   = T[9+i];
            }
        }

        // ---- dependency chain: immediate round + early-exit pointer jumping ----
        int dd = s_tdep[my_rt * 8 + li];
        int ptr;
        float val[12];
        {
            int s0l = base + dd;
            float pb[12];
#pragma unroll
            for (int k = 0; k < 12; k++)
                pb[k] = __shfl_sync(FULLM, o[k], s0l, 32);
            float nv[12];
            combine_tf(pb, o, nv);
            bool imm = (li != 0) && (dd >= li);
            bool done = (li == 0) || imm;
            ptr = done ? -1 : (base + dd);
#pragma unroll
            for (int k = 0; k < 12; k++)
                val[k] = imm ? nv[k] : o[k];
        }
        for (int rnd = 0; rnd < 3; rnd++) {
            if (__all_sync(FULLM, ptr < 0)) break;
            int ps = (ptr >= 0) ? ptr : lane;
            float pvv[12];
#pragma unroll
            for (int k = 0; k < 12; k++)
                pvv[k] = __shfl_sync(FULLM, val[k], ps, 32);
            int pp = __shfl_sync(FULLM, ptr, ps, 32);
            float nv[12];
            combine_tf(pvv, val, nv);
            bool live = (ptr >= 0);
#pragma unroll
            for (int k = 0; k < 12; k++)
                val[k] = live ? nv[k] : val[k];
            ptr = live ? pp : ptr;
        }

        // ---- atom gather: 3 atoms/lane, rigid vecs from reformatted table ----
        const float4* rp = reinterpret_cast<const float4*>(d_r2) + e * 24;
#pragma unroll
        for (int asub = 0; asub < 3; asub++) {
            int a = li * 3 + asub;
            int rd = s_rdep[my_rt * 24 + a];
            int gsrc = base + rd;
            float g[12];
#pragma unroll
            for (int k = 0; k < 12; k++)
                g[k] = __shfl_sync(FULLM, val[k], gsrc, 32);
            float4 rv = rp[asub * 8 + li];
            float* sp = &s_out[w][grp * 72 + a * 3];  // bank-conflict-free
            sp[0] = g[0]*rv.x + g[1]*rv.y + g[2]*rv.z + g[9];
            sp[1] = g[3]*rv.x + g[4]*rv.y + g[5]*rv.z + g[10];
            sp[2] = g[6]*rv.x + g[7]*rv.y + g[8]*rv.z + g[11];
        }

        // ---- opr[:,0]: direct STG.128 from leader lanes ----
        if (li == 0 && valid) {
            float4* dO = reinterpret_cast<float4*>(outO + (size_t)r * 12);
            dO[0] = make_float4(val[0], val[1], val[2],  val[3]);
            dO[1] = make_float4(val[4], val[5], val[6],  val[7]);
            dO[2] = make_float4(val[8], val[9], val[10], val[11]);
        }
        __syncwarp();

        // ---- coalesced R flush ----
        int nR4 = nres * 18;
        const float4* s4 = reinterpret_cast<const float4*>(&s_out[w][0]);
        float4* dR = reinterpret_cast<float4*>(outR + (size_t)r0 * 72);
        for (int i = lane; i < nR4; i += 32)
            dR[i] = s4[i];
        __syncwarp();
    }
}

extern "C" void kernel_launch(void* const* d_in, const int* in_sizes, int n_in,
                              void* d_out, int out_size) {
    const float* out0 = (const float*)d_in[0];
    const float* out1 = (const float*)d_in[1];
    const float* posp = (const float*)d_in[2];
    const int*   ssp  = (const int*)d_in[3];
    const int*   rtp  = (const int*)d_in[4];
    const float* gt   = (const float*)d_in[5];
    const float* gr   = (const float*)d_in[6];
    const int*   td   = (const int*)d_in[7];
    const int*   rd   = (const int*)d_in[8];
    int N = in_sizes[3];
    float* R = (float*)d_out;
    float* O = R + (size_t)N * 72;

    reformat_kernel<<<NE, 96>>>(gt, gr);
    struct_module_kernel<<<592, 256>>>(out0, out1, posp, ssp, rtp,
                                       td, rd, R, O, N);
}

// round 6
// speedup vs baseline: 1.4213x; 1.0319x over previous
#include <cuda_runtime.h>

// Model_21569325760600: structure-module forward.
// 8 lanes/residue, 4 residues/warp. Chain via pointer-jumping shuffles with
// STATIC precomputed jump tables (pure function of tdep) + warp-uniform early
// exit. Tables reformatted into line-coalesced layouts. 5 blocks/SM.

#define NRES  22
#define NE    66
#define FULLM 0xffffffffu

// reformatted tables: [e][chunk(3)][li(8)][4] floats = 96 floats per entry
__device__ __align__(16) float d_t2[NE * 96];
__device__ __align__(16) float d_r2[NE * 96];
// packed chain info per (rt, li): b0 = dd | imm<<7, b1..b3 = jump srcs (0xFF dead)
__device__ int d_chain[NRES * 8];

__global__ void reformat_kernel(const float* __restrict__ g_trans,   // [66,8,12]
                                const float* __restrict__ g_rigid,   // [66,24,3]
                                const int*   __restrict__ g_tdep) {  // [22,8]
    __shared__ int sp[NRES][8];
    int t = threadIdx.x;
    if (blockIdx.x < NE) {
        if (t < 96) {
            int e = blockIdx.x;
            int j4 = t >> 5;             // chunk 0..2
            int li = (t >> 2) & 7;
            int k  = t & 3;
            d_t2[e * 96 + t] = g_trans[e * 96 + li * 12 + j4 * 4 + k];
            d_r2[e * 96 + t] = (k < 3) ? g_rigid[e * 72 + (li * 3 + j4) * 3 + k] : 0.0f;
        }
        return;
    }
    // block NE: chain jump-table precompute (pointer jumping is static per rt)
    if (t < NRES * 8) {
        int rt = t >> 3, li = t & 7;
        int dd = g_tdep[rt * 8 + li];
        int imm = (li != 0 && dd >= li) ? 1 : 0;
        int p0 = (li != 0 && dd < li) ? dd : -1;
        sp[rt][li] = p0;
        __syncthreads();
        int p1 = (p0 >= 0) ? sp[rt][p0] : -1;
        __syncthreads();
        sp[rt][li] = p1;
        __syncthreads();
        int p2 = (p1 >= 0) ? sp[rt][p1] : -1;
        d_chain[t] = (dd & 0x7F) | (imm << 7) |
                     ((p0 & 0xFF) << 8) | ((p1 & 0xFF) << 16) | ((p2 & 0xFF) << 24);
    }
}

__device__ __forceinline__ void combine_tf(const float* __restrict__ X,
                                           const float* __restrict__ Y,
                                           float* __restrict__ C) {
#pragma unroll
    for (int i = 0; i < 3; i++) {
#pragma unroll
        for (int j = 0; j < 3; j++)
            C[3*i+j] = X[3*i+0]*Y[0+j] + X[3*i+1]*Y[3+j] + X[3*i+2]*Y[6+j];
        C[9+i] = X[3*i+0]*Y[9] + X[3*i+1]*Y[10] + X[3*i+2]*Y[11] + X[9+i];
    }
}

__global__ __launch_bounds__(256, 5) void struct_module_kernel(
    const float* __restrict__ out0,      // [N,17]
    const float* __restrict__ out1,      // [N,9]
    const float* __restrict__ pos,       // [N,3]
    const int*   __restrict__ ss,        // [N]
    const int*   __restrict__ rtype,     // [N]
    const int*   __restrict__ g_rdep,    // [22,24]
    float* __restrict__ outR,            // [N,72]
    float* __restrict__ outO,            // [N,12]
    int N)
{
    __shared__ int   s_chain[NRES * 8];
    __shared__ int   s_rdpk[NRES * 8];   // packed rdep: 3 bytes per (rt, li)
    __shared__ float s_out[8][288];      // R staging

    for (int idx = threadIdx.x; idx < NRES * 8; idx += blockDim.x) {
        s_chain[idx] = d_chain[idx];
        int rt = idx >> 3, li = idx & 7;
        int r0v = g_rdep[rt * 24 + li * 3 + 0];
        int r1v = g_rdep[rt * 24 + li * 3 + 1];
        int r2v = g_rdep[rt * 24 + li * 3 + 2];
        s_rdpk[idx] = r0v | (r1v << 8) | (r2v << 16);
    }
    __syncthreads();

    const int lane = threadIdx.x & 31;
    const int w    = threadIdx.x >> 5;
    const int li   = lane & 7;
    const int grp  = lane >> 3;
    const int base = lane & ~7;
    const int warpGlobal = (blockIdx.x * blockDim.x + threadIdx.x) >> 5;
    const int totalWarps = (gridDim.x * blockDim.x) >> 5;

    for (int r0 = warpGlobal * 4; r0 < N; r0 += totalWarps * 4) {
        int rem = N - r0;
        int nres = (rem >= 4) ? 4 : rem;
        int r = r0 + grp;
        bool valid = (r < N);
        int rc = valid ? r : (N - 1);

        int my_ss = ss[rc];
        int my_rt = rtype[rc];
        int e = my_ss * NRES + my_rt;
        int cb  = s_chain[my_rt * 8 + li];
        int rp3 = s_rdpk[my_rt * 8 + li];

        // ---- T from reformatted table: 3 LDG.128, 1 line per group each ----
        float T[12];
        {
            const float4* tp = reinterpret_cast<const float4*>(d_t2) + e * 24;
            float4 a = tp[li], b = tp[8 + li], c = tp[16 + li];
            T[0]=a.x; T[1]=a.y; T[2]=a.z;  T[3]=a.w;
            T[4]=b.x; T[5]=b.y; T[6]=b.z;  T[7]=b.w;
            T[8]=c.x; T[9]=c.y; T[10]=c.z; T[11]=c.w;
        }

        // ---- coalesced bb inputs: out1 (36 floats) + pos (12 floats) ----
        int nf1 = nres * 9;
        int nfp = nres * 3;
        float a0 = (lane < nf1)      ? out1[(size_t)r0 * 9 + lane]      : 0.0f;
        float a1 = (lane + 32 < nf1) ? out1[(size_t)r0 * 9 + 32 + lane] : 0.0f;
        float p0 = (lane < nfp)      ? pos[(size_t)r0 * 3 + lane]       : 0.0f;

        float v[9];
#pragma unroll
        for (int j = 0; j < 9; j++)
            v[j] = __shfl_sync(FULLM, a0, (9 * grp + j) & 31, 32);
#pragma unroll
        for (int j = 5; j < 9; j++) {
            int hs = 9 * grp + j - 32;
            float hi = __shfl_sync(FULLM, a1, hs < 0 ? 0 : hs, 32);
            if (9 * grp + j >= 32) v[j] = hi;
        }
        float pv[3];
#pragma unroll
        for (int k = 0; k < 3; k++)
            pv[k] = __shfl_sync(FULLM, p0, 3 * grp + k, 32);

        // ---- local transform combined with T -> o ----
        float o[12];
        if (li == 0) {
            float v0x = v[0], v0y = v[1], v0z = v[2];
            float v1x = v[3], v1y = v[4], v1z = v[5];
            float n2a = v0x*v0x + v0y*v0y + v0z*v0z;
            float i0 = rsqrtf(fmaxf(n2a, 1e-12f));
            float e0x = v0x*i0, e0y = v0y*i0, e0z = v0z*i0;
            float d = e0x*v1x + e0y*v1y + e0z*v1z;
            float u1x = v1x - e0x*d, u1y = v1y - e0y*d, u1z = v1z - e0z*d;
            float n2b = u1x*u1x + u1y*u1y + u1z*u1z;
            float i1 = rsqrtf(fmaxf(n2b, 1e-12f));
            float e1x = u1x*i1, e1y = u1y*i1, e1z = u1z*i1;
            float e2x = e0y*e1z - e0z*e1y;
            float e2y = e0z*e1x - e0x*e1z;
            float e2z = e0x*e1y - e0y*e1x;
            float B[12];
            B[0]=e0x; B[1]=e1x; B[2]=e2x;
            B[3]=e0y; B[4]=e1y; B[5]=e2y;
            B[6]=e0z; B[7]=e1z; B[8]=e2z;
            B[9]  = 0.1f * v[6] + pv[0];
            B[10] = 0.1f * v[7] + pv[1];
            B[11] = 0.1f * v[8] + pv[2];
            combine_tf(T, B, o);
        } else {
            float c0 = out0[(size_t)rc * 17 + 2*(li-1)];
            float s0 = out0[(size_t)rc * 17 + 2*(li-1) + 1];
            float inv = rsqrtf(fmaxf(c0*c0 + s0*s0, 1e-12f));
            float c = c0 * inv, s = s0 * inv;
#pragma unroll
            for (int i = 0; i < 3; i++) {
                o[3*i+0] = T[3*i+0];
                o[3*i+1] = T[3*i+1]*c + T[3*i+2]*s;
                o[3*i+2] = T[3*i+2]*c - T[3*i+1]*s;
                o[9+i]   = T[9+i];
            }
        }

        // ---- chain: immediate round + static-table pointer jumping ----
        float val[12];
        {
            int dd = cb & 0x7F;
            int s0l = base + dd;
            float pb[12];
#pragma unroll
            for (int k = 0; k < 12; k++)
                pb[k] = __shfl_sync(FULLM, o[k], s0l, 32);
            float nv[12];
            combine_tf(pb, o, nv);
            bool imm = (cb & 0x80) != 0;
#pragma unroll
            for (int k = 0; k < 12; k++)
                val[k] = imm ? nv[k] : o[k];
        }
#pragma unroll
        for (int rnd = 0; rnd < 3; rnd++) {
            int sk = (cb >> (8 * (rnd + 1))) & 0xFF;
            bool live = (sk != 0xFF);
            if (__all_sync(FULLM, !live)) break;
            int ps = live ? (base + sk) : lane;
            float pvv[12];
#pragma unroll
            for (int k = 0; k < 12; k++)
                pvv[k] = __shfl_sync(FULLM, val[k], ps, 32);
            float nv[12];
            combine_tf(pvv, val, nv);
#pragma unroll
            for (int k = 0; k < 12; k++)
                val[k] = live ? nv[k] : val[k];
        }

        // ---- atom gather: 3 atoms/lane via shfl, rigids from table ----
        const float4* rp = reinterpret_cast<const float4*>(d_r2) + e * 24;
#pragma unroll
        for (int asub = 0; asub < 3; asub++) {
            int a = li * 3 + asub;
            int rd = (rp3 >> (8 * asub)) & 0xFF;
            int gsrc = base + rd;
            float g[12];
#pragma unroll
            for (int k = 0; k < 12; k++)
                g[k] = __shfl_sync(FULLM, val[k], gsrc, 32);
            float4 rv = rp[asub * 8 + li];
            float* sp = &s_out[w][grp * 72 + a * 3];  // bank-conflict-free
            sp[0] = g[0]*rv.x + g[1]*rv.y + g[2]*rv.z + g[9];
            sp[1] = g[3]*rv.x + g[4]*rv.y + g[5]*rv.z + g[10];
            sp[2] = g[6]*rv.x + g[7]*rv.y + g[8]*rv.z + g[11];
        }

        // ---- opr[:,0]: direct STG.128 from leader lanes ----
        if (li == 0 && valid) {
            float4* dO = reinterpret_cast<float4*>(outO + (size_t)r * 12);
            dO[0] = make_float4(val[0], val[1], val[2],  val[3]);
            dO[1] = make_float4(val[4], val[5], val[6],  val[7]);
            dO[2] = make_float4(val[8], val[9], val[10], val[11]);
        }
        __syncwarp();

        // ---- coalesced R flush ----
        int nR4 = nres * 18;
        const float4* s4 = reinterpret_cast<const float4*>(&s_out[w][0]);
        float4* dR = reinterpret_cast<float4*>(outR + (size_t)r0 * 72);
#pragma unroll
        for (int i = 0; i < 3; i++) {
            int idx = lane + i * 32;
            if (idx < nR4)
                dR[idx] = s4[idx];
        }
        __syncwarp();
    }
}

extern "C" void kernel_launch(void* const* d_in, const int* in_sizes, int n_in,
                              void* d_out, int out_size) {
    const float* out0 = (const float*)d_in[0];
    const float* out1 = (const float*)d_in[1];
    const float* posp = (const float*)d_in[2];
    const int*   ssp  = (const int*)d_in[3];
    const int*   rtp  = (const int*)d_in[4];
    const float* gt   = (const float*)d_in[5];
    const float* gr   = (const float*)d_in[6];
    const int*   td   = (const int*)d_in[7];
    const int*   rd   = (const int*)d_in[8];
    int N = in_sizes[3];
    float* R = (float*)d_out;
    float* O = R + (size_t)N * 72;

    reformat_kernel<<<NE + 1, 192>>>(gt, gr, td);
    struct_module_kernel<<<740, 256>>>(out0, out1, posp, ssp, rtp,
                                       rd, R, O, N);
}

// round 7
// speedup vs baseline: 1.4716x; 1.0354x over previous
#include <cuda_runtime.h>

// Model_21569325760600: structure-module forward.
// 8 lanes/residue, DUAL-STREAM: 8 residues/warp-iter as two independent
// 4-residue streams interleaved for ILP (chain shuffles are latency-bound).
// Static precomputed pointer-jump tables; line-coalesced reformatted tables.

#define NRES  22
#define NE    66
#define FULLM 0xffffffffu

// reformatted tables: [e][chunk(3)][li(8)][4] floats = 96 floats per entry
__device__ __align__(16) float d_t2[NE * 96];
__device__ __align__(16) float d_r2[NE * 96];
// packed chain info per (rt, li): b0 = dd | imm<<7, b1..b3 = jump srcs (0xFF dead)
__device__ int d_chain[NRES * 8];

__global__ void reformat_kernel(const float* __restrict__ g_trans,   // [66,8,12]
                                const float* __restrict__ g_rigid,   // [66,24,3]
                                const int*   __restrict__ g_tdep) {  // [22,8]
    __shared__ int sp[NRES][8];
    int t = threadIdx.x;
    if (blockIdx.x < NE) {
        if (t < 96) {
            int e = blockIdx.x;
            int j4 = t >> 5;
            int li = (t >> 2) & 7;
            int k  = t & 3;
            d_t2[e * 96 + t] = g_trans[e * 96 + li * 12 + j4 * 4 + k];
            d_r2[e * 96 + t] = (k < 3) ? g_rigid[e * 72 + (li * 3 + j4) * 3 + k] : 0.0f;
        }
        return;
    }
    if (t < NRES * 8) {
        int rt = t >> 3, li = t & 7;
        int dd = g_tdep[rt * 8 + li];
        int imm = (li != 0 && dd >= li) ? 1 : 0;
        int p0 = (li != 0 && dd < li) ? dd : -1;
        sp[rt][li] = p0;
        __syncthreads();
        int p1 = (p0 >= 0) ? sp[rt][p0] : -1;
        __syncthreads();
        sp[rt][li] = p1;
        __syncthreads();
        int p2 = (p1 >= 0) ? sp[rt][p1] : -1;
        d_chain[t] = (dd & 0x7F) | (imm << 7) |
                     ((p0 & 0xFF) << 8) | ((p1 & 0xFF) << 16) | ((p2 & 0xFF) << 24);
    }
}

__device__ __forceinline__ void combine_tf(const float* __restrict__ X,
                                           const float* __restrict__ Y,
                                           float* __restrict__ C) {
#pragma unroll
    for (int i = 0; i < 3; i++) {
#pragma unroll
        for (int j = 0; j < 3; j++)
            C[3*i+j] = X[3*i+0]*Y[0+j] + X[3*i+1]*Y[3+j] + X[3*i+2]*Y[6+j];
        C[9+i] = X[3*i+0]*Y[9] + X[3*i+1]*Y[10] + X[3*i+2]*Y[11] + X[9+i];
    }
}

// Front section for one 4-residue stream: compute post-base transform o[12],
// table index e, chain word cb, packed rdep rp3.
__device__ __forceinline__ void stream_front(
    const float* __restrict__ out0, const float* __restrict__ out1,
    const float* __restrict__ pos,
    const int* __restrict__ ss, const int* __restrict__ rtype,
    const int* __restrict__ s_chain, const int* __restrict__ s_rdpk,
    int r0s, int N, int lane, int li, int grp,
    float o[12], int& e, int& cb, int& rp3)
{
    int rem = N - r0s;
    int nres = (rem >= 4) ? 4 : (rem > 0 ? rem : 0);
    int r = r0s + grp;
    bool valid = (r >= 0) && (r < N) && (nres > 0);
    int rc = valid ? r : (N - 1);

    int my_ss = ss[rc];
    int my_rt = rtype[rc];
    e   = my_ss * NRES + my_rt;
    cb  = s_chain[my_rt * 8 + li];
    rp3 = s_rdpk[my_rt * 8 + li];

    // T from reformatted table: 3 LDG.128, 1 line per group each
    float T[12];
    {
        const float4* tp = reinterpret_cast<const float4*>(d_t2) + e * 24;
        float4 a = tp[li], b = tp[8 + li], c = tp[16 + li];
        T[0]=a.x; T[1]=a.y; T[2]=a.z;  T[3]=a.w;
        T[4]=b.x; T[5]=b.y; T[6]=b.z;  T[7]=b.w;
        T[8]=c.x; T[9]=c.y; T[10]=c.z; T[11]=c.w;
    }

    // coalesced bb inputs: out1 (36 floats) + pos (12 floats)
    int nf1 = nres * 9;
    int nfp = nres * 3;
    size_t b1 = (size_t)(r0s > 0 ? r0s : 0);
    float a0 = (lane < nf1)      ? out1[b1 * 9 + lane]      : 0.0f;
    float a1 = (lane + 32 < nf1) ? out1[b1 * 9 + 32 + lane] : 0.0f;
    float p0 = (lane < nfp)      ? pos[b1 * 3 + lane]       : 0.0f;

    float v[9];
#pragma unroll
    for (int j = 0; j < 9; j++)
        v[j] = __shfl_sync(FULLM, a0, (9 * grp + j) & 31, 32);
#pragma unroll
    for (int j = 5; j < 9; j++) {
        int hs = 9 * grp + j - 32;
        float hi = __shfl_sync(FULLM, a1, hs < 0 ? 0 : hs, 32);
        if (9 * grp + j >= 32) v[j] = hi;
    }
    float pv[3];
#pragma unroll
    for (int k = 0; k < 3; k++)
        pv[k] = __shfl_sync(FULLM, p0, 3 * grp + k, 32);

    if (li == 0) {
        float v0x = v[0], v0y = v[1], v0z = v[2];
        float v1x = v[3], v1y = v[4], v1z = v[5];
        float n2a = v0x*v0x + v0y*v0y + v0z*v0z;
        float i0 = rsqrtf(fmaxf(n2a, 1e-12f));
        float e0x = v0x*i0, e0y = v0y*i0, e0z = v0z*i0;
        float d = e0x*v1x + e0y*v1y + e0z*v1z;
        float u1x = v1x - e0x*d, u1y = v1y - e0y*d, u1z = v1z - e0z*d;
        float n2b = u1x*u1x + u1y*u1y + u1z*u1z;
        float i1 = rsqrtf(fmaxf(n2b, 1e-12f));
        float e1x = u1x*i1, e1y = u1y*i1, e1z = u1z*i1;
        float e2x = e0y*e1z - e0z*e1y;
        float e2y = e0z*e1x - e0x*e1z;
        float e2z = e0x*e1y - e0y*e1x;
        float B[12];
        B[0]=e0x; B[1]=e1x; B[2]=e2x;
        B[3]=e0y; B[4]=e1y; B[5]=e2y;
        B[6]=e0z; B[7]=e1z; B[8]=e2z;
        B[9]  = 0.1f * v[6] + pv[0];
        B[10] = 0.1f * v[7] + pv[1];
        B[11] = 0.1f * v[8] + pv[2];
        combine_tf(T, B, o);
    } else {
        float c0 = out0[(size_t)rc * 17 + 2*(li-1)];
        float s0 = out0[(size_t)rc * 17 + 2*(li-1) + 1];
        float inv = rsqrtf(fmaxf(c0*c0 + s0*s0, 1e-12f));
        float c = c0 * inv, s = s0 * inv;
#pragma unroll
        for (int i = 0; i < 3; i++) {
            o[3*i+0] = T[3*i+0];
            o[3*i+1] = T[3*i+1]*c + T[3*i+2]*s;
            o[3*i+2] = T[3*i+2]*c - T[3*i+1]*s;
            o[9+i]   = T[9+i];
        }
    }
}

__global__ __launch_bounds__(256, 3) void struct_module_kernel(
    const float* __restrict__ out0,      // [N,17]
    const float* __restrict__ out1,      // [N,9]
    const float* __restrict__ pos,       // [N,3]
    const int*   __restrict__ ss,        // [N]
    const int*   __restrict__ rtype,     // [N]
    const int*   __restrict__ g_rdep,    // [22,24]
    float* __restrict__ outR,            // [N,72]
    float* __restrict__ outO,            // [N,12]
    int N)
{
    __shared__ int   s_chain[NRES * 8];
    __shared__ int   s_rdpk[NRES * 8];
    __shared__ float s_out[8][576];      // R staging, 2 streams x 288

    for (int idx = threadIdx.x; idx < NRES * 8; idx += blockDim.x) {
        s_chain[idx] = d_chain[idx];
        int rt = idx >> 3, li = idx & 7;
        int r0v = g_rdep[rt * 24 + li * 3 + 0];
        int r1v = g_rdep[rt * 24 + li * 3 + 1];
        int r2v = g_rdep[rt * 24 + li * 3 + 2];
        s_rdpk[idx] = r0v | (r1v << 8) | (r2v << 16);
    }
    __syncthreads();

    const int lane = threadIdx.x & 31;
    const int w    = threadIdx.x >> 5;
    const int li   = lane & 7;
    const int grp  = lane >> 3;
    const int base = lane & ~7;
    const int warpGlobal = (blockIdx.x * blockDim.x + threadIdx.x) >> 5;
    const int totalWarps = (gridDim.x * blockDim.x) >> 5;

    for (int r0 = warpGlobal * 8; r0 < N; r0 += totalWarps * 8) {
        // ---- front sections (independent streams A, B) ----
        float vA[12], vB[12];
        int eA, cbA, rpA, eB, cbB, rpB;
        {
            float oA[12], oB[12];
            stream_front(out0, out1, pos, ss, rtype, s_chain, s_rdpk,
                         r0,     N, lane, li, grp, oA, eA, cbA, rpA);
            stream_front(out0, out1, pos, ss, rtype, s_chain, s_rdpk,
                         r0 + 4, N, lane, li, grp, oB, eB, cbB, rpB);

            // ---- immediate rounds, interleaved ----
            int sA = base + (cbA & 0x7F);
            int sB = base + (cbB & 0x7F);
            float pA[12], pB[12];
#pragma unroll
            for (int k = 0; k < 12; k++) {
                pA[k] = __shfl_sync(FULLM, oA[k], sA, 32);
                pB[k] = __shfl_sync(FULLM, oB[k], sB, 32);
            }
            float nA[12], nB[12];
            combine_tf(pA, oA, nA);
            combine_tf(pB, oB, nB);
            bool immA = (cbA & 0x80) != 0;
            bool immB = (cbB & 0x80) != 0;
#pragma unroll
            for (int k = 0; k < 12; k++) {
                vA[k] = immA ? nA[k] : oA[k];
                vB[k] = immB ? nB[k] : oB[k];
            }
        }

        // ---- pointer-jump rounds, both streams per round ----
#pragma unroll
        for (int rnd = 0; rnd < 3; rnd++) {
            int skA = (cbA >> (8 * (rnd + 1))) & 0xFF;
            int skB = (cbB >> (8 * (rnd + 1))) & 0xFF;
            bool liveA = (skA != 0xFF);
            bool liveB = (skB != 0xFF);
            if (!__any_sync(FULLM, liveA || liveB)) break;
            int psA = liveA ? (base + skA) : lane;
            int psB = liveB ? (base + skB) : lane;
            float pA[12], pB[12];
#pragma unroll
            for (int k = 0; k < 12; k++) {
                pA[k] = __shfl_sync(FULLM, vA[k], psA, 32);
                pB[k] = __shfl_sync(FULLM, vB[k], psB, 32);
            }
            float nA[12], nB[12];
            combine_tf(pA, vA, nA);
            combine_tf(pB, vB, nB);
#pragma unroll
            for (int k = 0; k < 12; k++) {
                vA[k] = liveA ? nA[k] : vA[k];
                vB[k] = liveB ? nB[k] : vB[k];
            }
        }

        // ---- atom gathers, both streams interleaved ----
        const float4* rptA = reinterpret_cast<const float4*>(d_r2) + eA * 24;
        const float4* rptB = reinterpret_cast<const float4*>(d_r2) + eB * 24;
#pragma unroll
        for (int asub = 0; asub < 3; asub++) {
            int a = li * 3 + asub;
            int gA = base + ((rpA >> (8 * asub)) & 0xFF);
            int gB = base + ((rpB >> (8 * asub)) & 0xFF);
            float ga[12], gb[12];
#pragma unroll
            for (int k = 0; k < 12; k++) {
                ga[k] = __shfl_sync(FULLM, vA[k], gA, 32);
                gb[k] = __shfl_sync(FULLM, vB[k], gB, 32);
            }
            float4 rvA = rptA[asub * 8 + li];
            float4 rvB = rptB[asub * 8 + li];
            float* spA = &s_out[w][grp * 72 + a * 3];
            float* spB = spA + 288;
            spA[0] = ga[0]*rvA.x + ga[1]*rvA.y + ga[2]*rvA.z + ga[9];
            spA[1] = ga[3]*rvA.x + ga[4]*rvA.y + ga[5]*rvA.z + ga[10];
            spA[2] = ga[6]*rvA.x + ga[7]*rvA.y + ga[8]*rvA.z + ga[11];
            spB[0] = gb[0]*rvB.x + gb[1]*rvB.y + gb[2]*rvB.z + gb[9];
            spB[1] = gb[3]*rvB.x + gb[4]*rvB.y + gb[5]*rvB.z + gb[10];
            spB[2] = gb[6]*rvB.x + gb[7]*rvB.y + gb[8]*rvB.z + gb[11];
        }

        // ---- opr[:,0]: direct STG.128 from leader lanes ----
        if (li == 0) {
            int rA = r0 + grp;
            if (rA < N) {
                float4* dO = reinterpret_cast<float4*>(outO + (size_t)rA * 12);
                dO[0] = make_float4(vA[0], vA[1], vA[2],  vA[3]);
                dO[1] = make_float4(vA[4], vA[5], vA[6],  vA[7]);
                dO[2] = make_float4(vA[8], vA[9], vA[10], vA[11]);
            }
            int rB = r0 + 4 + grp;
            if (rB < N) {
                float4* dO = reinterpret_cast<float4*>(outO + (size_t)rB * 12);
                dO[0] = make_float4(vB[0], vB[1], vB[2],  vB[3]);
                dO[1] = make_float4(vB[4], vB[5], vB[6],  vB[7]);
                dO[2] = make_float4(vB[8], vB[9], vB[10], vB[11]);
            }
        }
        __syncwarp();

        // ---- coalesced R flush, both streams ----
        int remA = N - r0;
        int nA4 = ((remA >= 4) ? 4 : remA) * 18;
        int remB = N - (r0 + 4);
        int nB4 = ((remB >= 4) ? 4 : (remB > 0 ? remB : 0)) * 18;
        const float4* s4a = reinterpret_cast<const float4*>(&s_out[w][0]);
        const float4* s4b = reinterpret_cast<const float4*>(&s_out[w][288]);
        float4* dRa = reinterpret_cast<float4*>(outR + (size_t)r0 * 72);
        float4* dRb = reinterpret_cast<float4*>(outR + (size_t)(r0 + 4) * 72);
#pragma unroll
        for (int i = 0; i < 3; i++) {
            int idx = lane + i * 32;
            if (idx < nA4) dRa[idx] = s4a[idx];
            if (idx < nB4) dRb[idx] = s4b[idx];
        }
        __syncwarp();
    }
}

extern "C" void kernel_launch(void* const* d_in, const int* in_sizes, int n_in,
                              void* d_out, int out_size) {
    const float* out0 = (const float*)d_in[0];
    const float* out1 = (const float*)d_in[1];
    const float* posp = (const float*)d_in[2];
    const int*   ssp  = (const int*)d_in[3];
    const int*   rtp  = (const int*)d_in[4];
    const float* gt   = (const float*)d_in[5];
    const float* gr   = (const float*)d_in[6];
    const int*   td   = (const int*)d_in[7];
    const int*   rd   = (const int*)d_in[8];
    int N = in_sizes[3];
    float* R = (float*)d_out;
    float* O = R + (size_t)N * 72;

    reformat_kernel<<<NE + 1, 192>>>(gt, gr, td);
    struct_module_kernel<<<444, 256>>>(out0, out1, posp, ssp, rtp,
                                       rd, R, O, N);
}

// round 8
// speedup vs baseline: 1.5087x; 1.0252x over previous
#include <cuda_runtime.h>

// Model_21569325760600: structure-module forward.
// 8 lanes/residue, dual-stream (8 residues/warp-iter). Chain via static
// pointer-jump tables; identity-parent trick removes per-round merges;
// rounds 2-3 skip per-stream. Leader lanes load bb inputs directly.

#define NRES  22
#define NE    66
#define FULLM 0xffffffffu

__device__ __align__(16) float d_t2[NE * 96];
__device__ __align__(16) float d_r2[NE * 96];
__device__ int d_chain[NRES * 8];

__global__ void reformat_kernel(const float* __restrict__ g_trans,   // [66,8,12]
                                const float* __restrict__ g_rigid,   // [66,24,3]
                                const int*   __restrict__ g_tdep) {  // [22,8]
    __shared__ int sp[NRES][8];
    int t = threadIdx.x;
    if (blockIdx.x < NE) {
        if (t < 96) {
            int e = blockIdx.x;
            int j4 = t >> 5;
            int li = (t >> 2) & 7;
            int k  = t & 3;
            d_t2[e * 96 + t] = g_trans[e * 96 + li * 12 + j4 * 4 + k];
            d_r2[e * 96 + t] = (k < 3) ? g_rigid[e * 72 + (li * 3 + j4) * 3 + k] : 0.0f;
        }
        return;
    }
    if (t < NRES * 8) {
        int rt = t >> 3, li = t & 7;
        int dd = g_tdep[rt * 8 + li];
        int imm = (li != 0 && dd >= li) ? 1 : 0;
        int p0 = (li != 0 && dd < li) ? dd : -1;
        sp[rt][li] = p0;
        __syncthreads();
        int p1 = (p0 >= 0) ? sp[rt][p0] : -1;
        __syncthreads();
        sp[rt][li] = p1;
        __syncthreads();
        int p2 = (p1 >= 0) ? sp[rt][p1] : -1;
        d_chain[t] = (dd & 0x7F) | (imm << 7) |
                     ((p0 & 0xFF) << 8) | ((p1 & 0xFF) << 16) | ((p2 & 0xFF) << 24);
    }
}

__device__ __forceinline__ void combine_tf(const float* __restrict__ X,
                                           const float* __restrict__ Y,
                                           float* __restrict__ C) {
#pragma unroll
    for (int i = 0; i < 3; i++) {
#pragma unroll
        for (int j = 0; j < 3; j++)
            C[3*i+j] = X[3*i+0]*Y[0+j] + X[3*i+1]*Y[3+j] + X[3*i+2]*Y[6+j];
        C[9+i] = X[3*i+0]*Y[9] + X[3*i+1]*Y[10] + X[3*i+2]*Y[11] + X[9+i];
    }
}

// One pointer-jump round for one stream. Identity-parent for dead lanes makes
// the combine unconditional (I∘val == val exactly). Returns false if whole
// warp dead for this stream (round skipped).
__device__ __forceinline__ bool jump_round(float val[12], int cb, int rnd,
                                           int base, int lane) {
    int sk = (cb >> (8 * (rnd + 1))) & 0xFF;
    bool live = (sk != 0xFF);
    if (!__any_sync(FULLM, live)) return false;
    int ps = live ? (base + sk) : lane;
    float p[12];
#pragma unroll
    for (int k = 0; k < 12; k++)
        p[k] = __shfl_sync(FULLM, val[k], ps, 32);
    // dead lanes: parent := identity
    p[0]  = live ? p[0]  : 1.0f;
    p[1]  = live ? p[1]  : 0.0f;
    p[2]  = live ? p[2]  : 0.0f;
    p[3]  = live ? p[3]  : 0.0f;
    p[4]  = live ? p[4]  : 1.0f;
    p[5]  = live ? p[5]  : 0.0f;
    p[6]  = live ? p[6]  : 0.0f;
    p[7]  = live ? p[7]  : 0.0f;
    p[8]  = live ? p[8]  : 1.0f;
    p[9]  = live ? p[9]  : 0.0f;
    p[10] = live ? p[10] : 0.0f;
    p[11] = live ? p[11] : 0.0f;
    float nw[12];
    combine_tf(p, val, nw);
#pragma unroll
    for (int k = 0; k < 12; k++)
        val[k] = nw[k];
    return true;
}

// Front for one 4-residue stream: post-base transform o[12] + table index e,
// chain word cb, packed rdep rp3. Leader lanes load bb inputs directly.
__device__ __forceinline__ void stream_front(
    const float* __restrict__ out0, const float* __restrict__ out1,
    const float* __restrict__ pos,
    const int* __restrict__ ss, const int* __restrict__ rtype,
    const int* __restrict__ s_chain, const int* __restrict__ s_rdpk,
    int r0s, int N, int li, int grp,
    float o[12], int& e, int& cb, int& rp3)
{
    int r = r0s + grp;
    bool valid = (r >= 0) && (r < N);
    int rc = valid ? r : (N - 1);

    int my_ss = ss[rc];
    int my_rt = rtype[rc];
    e   = my_ss * NRES + my_rt;
    cb  = s_chain[my_rt * 8 + li];
    rp3 = s_rdpk[my_rt * 8 + li];

    // T: 3 LDG.128, one 128B line per group each
    float T[12];
    {
        const float4* tp = reinterpret_cast<const float4*>(d_t2) + e * 24;
        float4 a = tp[li], b = tp[8 + li], c = tp[16 + li];
        T[0]=a.x; T[1]=a.y; T[2]=a.z;  T[3]=a.w;
        T[4]=b.x; T[5]=b.y; T[6]=b.z;  T[7]=b.w;
        T[8]=c.x; T[9]=c.y; T[10]=c.z; T[11]=c.w;
    }

    if (li == 0) {
        const float* p1 = out1 + (size_t)rc * 9;
        float v0x = __ldg(p1+0), v0y = __ldg(p1+1), v0z = __ldg(p1+2);
        float v1x = __ldg(p1+3), v1y = __ldg(p1+4), v1z = __ldg(p1+5);
        float t0  = __ldg(p1+6), t1  = __ldg(p1+7), t2  = __ldg(p1+8);
        const float* pp = pos + (size_t)rc * 3;
        float px = __ldg(pp+0), py = __ldg(pp+1), pz = __ldg(pp+2);

        float n2a = v0x*v0x + v0y*v0y + v0z*v0z;
        float i0 = rsqrtf(fmaxf(n2a, 1e-12f));
        float e0x = v0x*i0, e0y = v0y*i0, e0z = v0z*i0;
        float d = e0x*v1x + e0y*v1y + e0z*v1z;
        float u1x = v1x - e0x*d, u1y = v1y - e0y*d, u1z = v1z - e0z*d;
        float n2b = u1x*u1x + u1y*u1y + u1z*u1z;
        float i1 = rsqrtf(fmaxf(n2b, 1e-12f));
        float e1x = u1x*i1, e1y = u1y*i1, e1z = u1z*i1;
        float e2x = e0y*e1z - e0z*e1y;
        float e2y = e0z*e1x - e0x*e1z;
        float e2z = e0x*e1y - e0y*e1x;
        float B[12];
        B[0]=e0x; B[1]=e1x; B[2]=e2x;
        B[3]=e0y; B[4]=e1y; B[5]=e2y;
        B[6]=e0z; B[7]=e1z; B[8]=e2z;
        B[9]  = 0.1f * t0 + px;
        B[10] = 0.1f * t1 + py;
        B[11] = 0.1f * t2 + pz;
        combine_tf(T, B, o);
    } else {
        const float* q = out0 + (size_t)rc * 17 + 2*(li-1);
        float c0 = __ldg(q+0);
        float s0 = __ldg(q+1);
        float inv = rsqrtf(fmaxf(c0*c0 + s0*s0, 1e-12f));
        float c = c0 * inv, s = s0 * inv;
#pragma unroll
        for (int i = 0; i < 3; i++) {
            o[3*i+0] = T[3*i+0];
            o[3*i+1] = T[3*i+1]*c + T[3*i+2]*s;
            o[3*i+2] = T[3*i+2]*c - T[3*i+1]*s;
            o[9+i]   = T[9+i];
        }
    }
}

__global__ __launch_bounds__(192, 5) void struct_module_kernel(
    const float* __restrict__ out0,      // [N,17]
    const float* __restrict__ out1,      // [N,9]
    const float* __restrict__ pos,       // [N,3]
    const int*   __restrict__ ss,        // [N]
    const int*   __restrict__ rtype,     // [N]
    const int*   __restrict__ g_rdep,    // [22,24]
    float* __restrict__ outR,            // [N,72]
    float* __restrict__ outO,            // [N,12]
    int N)
{
    __shared__ int   s_chain[NRES * 8];
    __shared__ int   s_rdpk[NRES * 8];
    __shared__ float s_out[6][576];      // 6 warps x 2 streams x 288

    for (int idx = threadIdx.x; idx < NRES * 8; idx += blockDim.x) {
        s_chain[idx] = d_chain[idx];
        int rt = idx >> 3, li = idx & 7;
        int r0v = g_rdep[rt * 24 + li * 3 + 0];
        int r1v = g_rdep[rt * 24 + li * 3 + 1];
        int r2v = g_rdep[rt * 24 + li * 3 + 2];
        s_rdpk[idx] = r0v | (r1v << 8) | (r2v << 16);
    }
    __syncthreads();

    const int lane = threadIdx.x & 31;
    const int w    = threadIdx.x >> 5;
    const int li   = lane & 7;
    const int grp  = lane >> 3;
    const int base = lane & ~7;
    const int warpGlobal = (blockIdx.x * blockDim.x + threadIdx.x) >> 5;
    const int totalWarps = (gridDim.x * blockDim.x) >> 5;

    for (int r0 = warpGlobal * 8; r0 < N; r0 += totalWarps * 8) {
        float vA[12], vB[12];
        int eA, cbA, rpA, eB, cbB, rpB;
        {
            float oA[12], oB[12];
            stream_front(out0, out1, pos, ss, rtype, s_chain, s_rdpk,
                         r0,     N, li, grp, oA, eA, cbA, rpA);
            stream_front(out0, out1, pos, ss, rtype, s_chain, s_rdpk,
                         r0 + 4, N, li, grp, oB, eB, cbB, rpB);

            // immediate round, dual-interleaved
            int sA = base + (cbA & 0x7F);
            int sB = base + (cbB & 0x7F);
            float pA[12], pB[12];
#pragma unroll
            for (int k = 0; k < 12; k++) {
                pA[k] = __shfl_sync(FULLM, oA[k], sA, 32);
                pB[k] = __shfl_sync(FULLM, oB[k], sB, 32);
            }
            float nA[12], nB[12];
            combine_tf(pA, oA, nA);
            combine_tf(pB, oB, nB);
            bool immA = (cbA & 0x80) != 0;
            bool immB = (cbB & 0x80) != 0;
#pragma unroll
            for (int k = 0; k < 12; k++) {
                vA[k] = immA ? nA[k] : oA[k];
                vB[k] = immB ? nB[k] : oB[k];
            }
        }

        // round 1 (usually live for both): per-stream bodies back-to-back
        bool goA = jump_round(vA, cbA, 0, base, lane);
        bool goB = jump_round(vB, cbB, 0, base, lane);
        // rounds 2-3: per-stream skip
        if (goA) { if (jump_round(vA, cbA, 1, base, lane)) jump_round(vA, cbA, 2, base, lane); }
        if (goB) { if (jump_round(vB, cbB, 1, base, lane)) jump_round(vB, cbB, 2, base, lane); }

        // ---- atom gathers, per stream (register-pressure friendly) ----
        {
            const float4* rpt = reinterpret_cast<const float4*>(d_r2) + eA * 24;
#pragma unroll
            for (int asub = 0; asub < 3; asub++) {
                int a = li * 3 + asub;
                int gsrc = base + ((rpA >> (8 * asub)) & 0xFF);
                float g[12];
#pragma unroll
                for (int k = 0; k < 12; k++)
                    g[k] = __shfl_sync(FULLM, vA[k], gsrc, 32);
                float4 rv = rpt[asub * 8 + li];
                float* sp = &s_out[w][grp * 72 + a * 3];
                sp[0] = g[0]*rv.x + g[1]*rv.y + g[2]*rv.z + g[9];
                sp[1] = g[3]*rv.x + g[4]*rv.y + g[5]*rv.z + g[10];
                sp[2] = g[6]*rv.x + g[7]*rv.y + g[8]*rv.z + g[11];
            }
        }
        {
            const float4* rpt = reinterpret_cast<const float4*>(d_r2) + eB * 24;
#pragma unroll
            for (int asub = 0; asub < 3; asub++) {
                int a = li * 3 + asub;
                int gsrc = base + ((rpB >> (8 * asub)) & 0xFF);
                float g[12];
#pragma unroll
                for (int k = 0; k < 12; k++)
                    g[k] = __shfl_sync(FULLM, vB[k], gsrc, 32);
                float4 rv = rpt[asub * 8 + li];
                float* sp = &s_out[w][288 + grp * 72 + a * 3];
                sp[0] = g[0]*rv.x + g[1]*rv.y + g[2]*rv.z + g[9];
                sp[1] = g[3]*rv.x + g[4]*rv.y + g[5]*rv.z + g[10];
                sp[2] = g[6]*rv.x + g[7]*rv.y + g[8]*rv.z + g[11];
            }
        }

        // ---- opr[:,0]: direct STG.128 from leader lanes ----
        if (li == 0) {
            int rA = r0 + grp;
            if (rA < N) {
                float4* dO = reinterpret_cast<float4*>(outO + (size_t)rA * 12);
                dO[0] = make_float4(vA[0], vA[1], vA[2],  vA[3]);
                dO[1] = make_float4(vA[4], vA[5], vA[6],  vA[7]);
                dO[2] = make_float4(vA[8], vA[9], vA[10], vA[11]);
            }
            int rB = r0 + 4 + grp;
            if (rB < N) {
                float4* dO = reinterpret_cast<float4*>(outO + (size_t)rB * 12);
                dO[0] = make_float4(vB[0], vB[1], vB[2],  vB[3]);
                dO[1] = make_float4(vB[4], vB[5], vB[6],  vB[7]);
                dO[2] = make_float4(vB[8], vB[9], vB[10], vB[11]);
            }
        }
        __syncwarp();

        // ---- coalesced R flush ----
        int remA = N - r0;
        int nA4 = ((remA >= 4) ? 4 : remA) * 18;
        int remB = N - (r0 + 4);
        int nB4 = ((remB >= 4) ? 4 : (remB > 0 ? remB : 0)) * 18;
        const float4* s4a = reinterpret_cast<const float4*>(&s_out[w][0]);
        const float4* s4b = reinterpret_cast<const float4*>(&s_out[w][288]);
        float4* dRa = reinterpret_cast<float4*>(outR + (size_t)r0 * 72);
        float4* dRb = reinterpret_cast<float4*>(outR + (size_t)(r0 + 4) * 72);
#pragma unroll
        for (int i = 0; i < 3; i++) {
            int idx = lane + i * 32;
            if (idx < nA4) dRa[idx] = s4a[idx];
            if (idx < nB4) dRb[idx] = s4b[idx];
        }
        __syncwarp();
    }
}

extern "C" void kernel_launch(void* const* d_in, const int* in_sizes, int n_in,
                              void* d_out, int out_size) {
    const float* out0 = (const float*)d_in[0];
    const float* out1 = (const float*)d_in[1];
    const float* posp = (const float*)d_in[2];
    const int*   ssp  = (const int*)d_in[3];
    const int*   rtp  = (const int*)d_in[4];
    const float* gt   = (const float*)d_in[5];
    const float* gr   = (const float*)d_in[6];
    const int*   td   = (const int*)d_in[7];
    const int*   rd   = (const int*)d_in[8];
    int N = in_sizes[3];
    float* R = (float*)d_out;
    float* O = R + (size_t)N * 72;

    reformat_kernel<<<NE + 1, 192>>>(gt, gr, td);
    struct_module_kernel<<<740, 192>>>(out0, out1, posp, ssp, rtp,
                                       rd, R, O, N);
}